// round 3
// baseline (speedup 1.0000x reference)
#include <cuda_runtime.h>
#include <math.h>

#define BB  8
#define MM  36
#define DD  512
#define HWW 196
#define TT  64
#define NN  7056          // MM*HWW
#define PP  64            // BB*BB pairs
#define G1  4.0f
#define G2  5.0f
#define KSPLIT 4
#define KRANGE (NN / KSPLIT)   // 1764 = 63 * 28
#define KC2 28

// ---------------- scratch (device globals; no allocation) ----------------
__device__ float d_V[BB * NN * DD];             // (B, N, D) region features
__device__ float d_W4[PP * TT * NN];            // exp(4*norm_sim) per pair
__device__ float d_Gs[KSPLIT][PP * TT * DD];    // split partial v_tidal
__device__ float d_normsq[BB * NN];             // per-region squared norms
__device__ float d_u[BB * MM * DD];             // sum of normalized rows per box
__device__ float d_Zt[PP * TT];                 // attn denominators
__device__ float d_sExp[PP * TT * MM];          // per-box sums of exp(norm_sim)
__device__ float d_S[PP];                       // pair scores
__device__ float d_betas[BB * TT * MM];         // diagonal betas

// ---------------- packed f32x2 helpers ----------------
__device__ __forceinline__ unsigned long long pack2(float a) {
    unsigned long long r;
    asm("mov.b64 %0, {%1, %1};" : "=l"(r) : "r"(__float_as_uint(a)));
    return r;
}
__device__ __forceinline__ void unpack2(unsigned long long v, float& lo, float& hi) {
    unsigned int l, h;
    asm("mov.b64 {%0, %1}, %2;" : "=r"(l), "=r"(h) : "l"(v));
    lo = __uint_as_float(l);
    hi = __uint_as_float(h);
}
__device__ __forceinline__ void fma2(unsigned long long& d,
                                     unsigned long long a, unsigned long long b) {
    asm("fma.rn.f32x2 %0, %1, %2, %0;" : "+l"(d) : "l"(a), "l"(b));
}

// ---------------- kernel 0: zero accumulators ----------------
__global__ void k_init() {
    int idx = blockIdx.x * blockDim.x + threadIdx.x;
    if (idx < BB * NN)       d_normsq[idx] = 0.f;
    if (idx < PP * TT)       d_Zt[idx]     = 0.f;
    if (idx < PP * TT * MM)  d_sExp[idx]   = 0.f;
}

// ---------------- kernel 1: transpose image -> V, accumulate norms ----------------
__global__ void __launch_bounds__(256) k_transpose(const float* __restrict__ image) {
    __shared__ float tile[32 * 197];
    const int b = blockIdx.z, m = blockIdx.y, d0 = blockIdx.x * 32;
    const float* src = image + ((size_t)(b * MM + m) * DD + d0) * HWW;
    for (int idx = threadIdx.x; idx < 32 * HWW; idx += 256) {
        int dd = idx / HWW, hw = idx % HWW;
        tile[dd * 197 + hw] = src[idx];
    }
    __syncthreads();
    float* dst = d_V + (size_t)(b * NN + m * HWW) * DD + d0;
    for (int idx = threadIdx.x; idx < HWW * 32; idx += 256) {
        int nl = idx >> 5, dd = idx & 31;
        int w = nl / 14, h = nl % 14;                 // nl = w*14 + h
        dst[(size_t)nl * DD + dd] = tile[dd * 197 + h * 14 + w];
    }
    if (threadIdx.x < HWW) {
        int nl = threadIdx.x;
        int w = nl / 14, h = nl % 14;
        float s = 0.f;
        #pragma unroll
        for (int dd = 0; dd < 32; dd++) {
            float v = tile[dd * 197 + h * 14 + w];
            s = fmaf(v, v, s);
        }
        atomicAdd(&d_normsq[b * NN + m * HWW + nl], s);
    }
}

// ---------------- kernel 2: u[b,m,d] = sum_hw V / ||V_row|| ----------------
__global__ void __launch_bounds__(256) k_u() {
    const int m = blockIdx.x, b = blockIdx.y;
    __shared__ float inv[HWW];
    if (threadIdx.x < HWW)
        inv[threadIdx.x] = rsqrtf(d_normsq[b * NN + m * HWW + threadIdx.x]);
    __syncthreads();
    const float* vb = d_V + (size_t)(b * NN + m * HWW) * DD;
    for (int d = threadIdx.x; d < DD; d += 256) {
        float acc = 0.f;
        for (int hw = 0; hw < HWW; hw++)
            acc = fmaf(vb[(size_t)hw * DD + d], inv[hw], acc);
        d_u[(size_t)(b * MM + m) * DD + d] = acc;
    }
}

// ---------------- kernel 3: sim GEMM (packed f32x2, coalesced LDS) ----------------
// Block: one pair p, 256-column tile of n. 64x256 tile, 8 rows x (4+4 split cols).
// C[t][n] = sum_k E[t][k] * V[n][k]
__global__ void __launch_bounds__(256) k_sim(const float* __restrict__ text) {
    const int p = blockIdx.y;
    const int i = p >> 3, j = p & 7;
    const int n0 = blockIdx.x * 256;

    __shared__ float sm[64 * 130];        // GEMM tiles, later Cs staging
    __shared__ float psum[64 * 2 * 4];
    __shared__ int   colm[128];
    float* As = sm;                       // [16][64]  k-major
    float* Bs = sm + 16 * 64;             // [16][260] k-major

    unsigned long long acc[8][4];
    #pragma unroll
    for (int r = 0; r < 8; r++)
        #pragma unroll
        for (int c = 0; c < 4; c++) acc[r][c] = 0ull;

    const int tx = threadIdx.x & 31, ty = threadIdx.x >> 5;
    const float* E  = text + (size_t)j * TT * DD;
    const float* Vi = d_V + (size_t)i * NN * DD;
    const int tA_t = threadIdx.x & 63;
    const int tA_k = (threadIdx.x >> 6) * 4;

    for (int k0 = 0; k0 < DD; k0 += 16) {
        __syncthreads();
        // As: E[t][k0+k] -> As[k][t]
        {
            float4 av = *(const float4*)&E[(size_t)tA_t * DD + k0 + tA_k];
            As[(tA_k + 0) * 64 + tA_t] = av.x;
            As[(tA_k + 1) * 64 + tA_t] = av.y;
            As[(tA_k + 2) * 64 + tA_t] = av.z;
            As[(tA_k + 3) * 64 + tA_t] = av.w;
        }
        // Bs: V[n][k0+k] -> Bs[k][n]
        #pragma unroll
        for (int r = 0; r < 4; r++) {
            int id = threadIdx.x + r * 256;   // [0,1024)
            int n = id >> 2, kq = (id & 3) * 4;
            int gn = n0 + n;
            float4 bv = (gn < NN) ? *(const float4*)&Vi[(size_t)gn * DD + k0 + kq]
                                  : make_float4(0.f, 0.f, 0.f, 0.f);
            Bs[(kq + 0) * 260 + n] = bv.x;
            Bs[(kq + 1) * 260 + n] = bv.y;
            Bs[(kq + 2) * 260 + n] = bv.z;
            Bs[(kq + 3) * 260 + n] = bv.w;
        }
        __syncthreads();
        #pragma unroll
        for (int kk = 0; kk < 16; kk++) {
            float4 a0 = *(const float4*)&As[kk * 64 + ty * 8];
            float4 a1 = *(const float4*)&As[kk * 64 + ty * 8 + 4];
            unsigned long long a2[8];
            a2[0] = pack2(a0.x); a2[1] = pack2(a0.y);
            a2[2] = pack2(a0.z); a2[3] = pack2(a0.w);
            a2[4] = pack2(a1.x); a2[5] = pack2(a1.y);
            a2[6] = pack2(a1.z); a2[7] = pack2(a1.w);
            // coalesced: lane tx reads 16B at byte 16*tx (both halves)
            ulonglong2 B0 = *(const ulonglong2*)&Bs[kk * 260 + tx * 4];
            ulonglong2 B1 = *(const ulonglong2*)&Bs[kk * 260 + 128 + tx * 4];
            unsigned long long b2[4] = {B0.x, B0.y, B1.x, B1.y};
            #pragma unroll
            for (int r = 0; r < 8; r++)
                #pragma unroll
                for (int c = 0; c < 4; c++)
                    fma2(acc[r][c], a2[r], b2[c]);
        }
    }

    // ---------------- epilogue: two halves of 128 columns ----------------
    // thread (tx,ty) owns rows ty*8..+7, cols {tx*4..+3} (h=0) and {128+tx*4..+3} (h=1)
    const int m_base = n0 / HWW;
    float* Cs = sm;                        // [64][130]
    for (int h = 0; h < 2; h++) {
        __syncthreads();
        #pragma unroll
        for (int r = 0; r < 8; r++)
            #pragma unroll
            for (int q = 0; q < 2; q++) {
                float lo, hi;
                unpack2(acc[r][h * 2 + q], lo, hi);
                Cs[(ty * 8 + r) * 130 + tx * 4 + q * 2]     = lo;
                Cs[(ty * 8 + r) * 130 + tx * 4 + q * 2 + 1] = hi;
            }
        __syncthreads();
        // column phase: softmax over t for each column
        if (threadIdx.x < 128) {
            const int col = threadIdx.x;
            const int n = n0 + h * 128 + col;
            const bool valid = (n < NN);
            colm[col] = valid ? (n / HWW - m_base) : -1;
            float mx = -1e30f;
            for (int t = 0; t < TT; t++) mx = fmaxf(mx, Cs[t * 130 + col]);
            float ssum = 0.f;
            for (int t = 0; t < TT; t++) {
                float e = __expf(Cs[t * 130 + col] - mx);
                ssum += e;
                Cs[t * 130 + col] = e;
            }
            const float inv_s = 1.0f / ssum;
            if (valid) {
                float* w4p = d_W4 + (size_t)p * TT * NN + n;
                for (int t = 0; t < TT; t++) {
                    float ns = Cs[t * 130 + col] * inv_s;  // norm_sim
                    float en = __expf(ns);
                    Cs[t * 130 + col] = en;
                    float e4 = en * en; e4 *= e4;          // exp(4*ns)
                    w4p[(size_t)t * NN] = e4;
                }
            } else {
                for (int t = 0; t < TT; t++) Cs[t * 130 + col] = 0.f;
            }
        }
        __syncthreads();
        // row phase: reduce over columns per t
        if (threadIdx.x < 128) {
            const int t = threadIdx.x >> 1, half = threadIdx.x & 1;
            float z = 0.f, s0 = 0.f, s1 = 0.f, s2 = 0.f;
            const int c0 = half * 64;
            for (int c = c0; c < c0 + 64; c++) {
                float en = Cs[t * 130 + c];
                float e4 = en * en; e4 *= e4;
                z += e4;
                int bm = colm[c];
                s0 += (bm == 0) ? en : 0.f;
                s1 += (bm == 1) ? en : 0.f;
                s2 += (bm == 2) ? en : 0.f;
            }
            float* pp = &psum[(t * 2 + half) * 4];
            pp[0] = z; pp[1] = s0; pp[2] = s1; pp[3] = s2;
        }
        __syncthreads();
        if (threadIdx.x < 64) {
            const int t = threadIdx.x;
            const float* p0 = &psum[(t * 2) * 4];
            const float* p1 = &psum[(t * 2 + 1) * 4];
            atomicAdd(&d_Zt[p * TT + t], p0[0] + p1[0]);
            #pragma unroll
            for (int bm = 0; bm < 3; bm++) {
                float s = p0[1 + bm] + p1[1 + bm];
                int m = m_base + bm;
                if (m < MM && s != 0.f)
                    atomicAdd(&d_sExp[(size_t)(p * TT + t) * MM + m], s);
            }
        }
    }
}

// ---------------- kernel 4: Gs[s][p,t,d] = sum_{n in split s} W4[p,t,n] * V[i,n,d]
// Block: pair p, 256-d tile, 1/4 of the n range. Split-column layout, plain stores.
__global__ void __launch_bounds__(256) k_gmm() {
    const int p = blockIdx.z;
    const int i = p >> 3;
    const int d0 = blockIdx.x * 256;
    const int s = blockIdx.y;
    const int kb0 = s * KRANGE;

    __shared__ float As[KC2 * 68];        // [28][68]  (W4, k-major, 16B-aligned rows)
    __shared__ float Bs[KC2 * 260];       // [28][260] (V, k-major)

    unsigned long long acc[8][4];
    #pragma unroll
    for (int r = 0; r < 8; r++)
        #pragma unroll
        for (int c = 0; c < 4; c++) acc[r][c] = 0ull;

    const int tx = threadIdx.x & 31, ty = threadIdx.x >> 5;
    const float* Wp = d_W4 + (size_t)p * TT * NN;
    const float* Vi = d_V + (size_t)i * NN * DD;

    for (int kc = 0; kc < KRANGE / KC2; kc++) {
        const int kb = kb0 + kc * KC2;
        __syncthreads();
        // As: W4[t][kb+k] -> As[k][t]   (1792 elems, 7 per thread)
        #pragma unroll
        for (int r = 0; r < 7; r++) {
            int id = threadIdx.x + r * 256;
            int t = id / KC2, k = id % KC2;
            As[k * 68 + t] = Wp[(size_t)t * NN + kb + k];
        }
        // Bs: V[kb+k][d0+d]  (7168 floats = 1792 float4, 7 per thread)
        #pragma unroll
        for (int r = 0; r < 7; r++) {
            int id = threadIdx.x + r * 256;
            int k = id >> 6, dq = (id & 63) * 4;
            float4 bv = *(const float4*)&Vi[(size_t)(kb + k) * DD + d0 + dq];
            Bs[k * 260 + dq + 0] = bv.x;
            Bs[k * 260 + dq + 1] = bv.y;
            Bs[k * 260 + dq + 2] = bv.z;
            Bs[k * 260 + dq + 3] = bv.w;
        }
        __syncthreads();
        #pragma unroll
        for (int kk = 0; kk < KC2; kk++) {
            float4 a0 = *(const float4*)&As[kk * 68 + ty * 8];
            float4 a1 = *(const float4*)&As[kk * 68 + ty * 8 + 4];
            unsigned long long a2[8];
            a2[0] = pack2(a0.x); a2[1] = pack2(a0.y);
            a2[2] = pack2(a0.z); a2[3] = pack2(a0.w);
            a2[4] = pack2(a1.x); a2[5] = pack2(a1.y);
            a2[6] = pack2(a1.z); a2[7] = pack2(a1.w);
            ulonglong2 B0 = *(const ulonglong2*)&Bs[kk * 260 + tx * 4];
            ulonglong2 B1 = *(const ulonglong2*)&Bs[kk * 260 + 128 + tx * 4];
            unsigned long long b2[4] = {B0.x, B0.y, B1.x, B1.y};
            #pragma unroll
            for (int r = 0; r < 8; r++)
                #pragma unroll
                for (int c = 0; c < 4; c++)
                    fma2(acc[r][c], a2[r], b2[c]);
        }
    }

    float* Gp = &d_Gs[s][(size_t)p * TT * DD + d0];
    #pragma unroll
    for (int r = 0; r < 8; r++)
        #pragma unroll
        for (int ch = 0; ch < 2; ch++) {
            float lo0, hi0, lo1, hi1;
            unpack2(acc[r][ch * 2 + 0], lo0, hi0);
            unpack2(acc[r][ch * 2 + 1], lo1, hi1);
            *(float4*)&Gp[(size_t)(ty * 8 + r) * DD + ch * 128 + tx * 4] =
                make_float4(lo0, hi0, lo1, hi1);
        }
}

// ---------------- kernel 5: per-pair score S[p] ----------------
__global__ void __launch_bounds__(256) k_score(const float* __restrict__ text) {
    const int p = blockIdx.x, i = p >> 3, j = p & 7;
    __shared__ float sbeta[TT * MM];
    __shared__ float sls[MM];
    __shared__ float sdiag[TT];
    __shared__ float snrm[MM], sdot[MM];
    __shared__ float Es[TT * 128];
    const int tid = threadIdx.x, lane = tid & 31, warp = tid >> 5;
    const float* E = text + (size_t)j * TT * DD;

    for (int idx = tid; idx < TT * MM; idx += 256)
        sbeta[idx] = d_sExp[(size_t)p * TT * MM + idx];
    if (tid < MM) { snrm[tid] = 0.f; sdot[tid] = 0.f; }
    __syncthreads();
    if (tid < MM) {
        float s = 0.f;
        for (int t = 0; t < TT; t++) s += sbeta[t * MM + tid];
        sls[tid] = 1.0f / s;
    }
    __syncthreads();
    for (int idx = tid; idx < TT * MM; idx += 256) {
        float v = sbeta[idx] * sls[idx % MM];
        sbeta[idx] = v;
        if (i == j) d_betas[(size_t)i * TT * MM + idx] = v;
    }
    __syncthreads();

    // diag[t] = (sum_s Gs[s][t]) . e[t] / Zt
    for (int t = warp; t < TT; t += 8) {
        const size_t off = ((size_t)p * TT + t) * DD;
        const float* Er = E + (size_t)t * DD;
        float s = 0.f;
        for (int d = lane; d < DD; d += 32) {
            float g = d_Gs[0][off + d] + d_Gs[1][off + d]
                    + d_Gs[2][off + d] + d_Gs[3][off + d];
            s = fmaf(g, Er[d], s);
        }
        #pragma unroll
        for (int off2 = 16; off2; off2 >>= 1) s += __shfl_down_sync(0xffffffffu, s, off2);
        if (lane == 0) sdiag[t] = s / d_Zt[p * TT + t];
    }

    const float* U = d_u + (size_t)i * MM * DD;
    const int grp = tid >> 7;
    const int dl = tid & 127;
    for (int d0 = 0; d0 < DD; d0 += 128) {
        __syncthreads();
        for (int idx = tid; idx < TT * 128; idx += 256) {
            int t = idx >> 7, dloc = idx & 127;
            Es[idx] = E[(size_t)t * DD + d0 + dloc];
        }
        __syncthreads();
        for (int m = grp; m < MM; m += 2) {
            float v = 0.f;
            #pragma unroll 16
            for (int t = 0; t < TT; t++)
                v = fmaf(sbeta[t * MM + m], Es[t * 128 + dl], v);
            float nr = v * v;
            float dt = v * U[(size_t)m * DD + d0 + dl];
            #pragma unroll
            for (int off = 16; off; off >>= 1) {
                nr += __shfl_down_sync(0xffffffffu, nr, off);
                dt += __shfl_down_sync(0xffffffffu, dt, off);
            }
            if (lane == 0) { atomicAdd(&snrm[m], nr); atomicAdd(&sdot[m], dt); }
        }
    }
    __syncthreads();
    if (tid == 0) {
        float se = 0.f;
        for (int t = 0; t < TT; t++) se += expf(G2 * sdiag[t]);
        float r_qd = (1.0f / G2) * logf(se);
        float sm = 0.f;
        for (int m = 0; m < MM; m++)
            sm += expf(sdot[m] / ((float)HWW * sqrtf(snrm[m])));
        d_S[p] = r_qd + (1.0f / G2) * logf(sm);
    }
}

// ---------------- kernel 6: final scalar ----------------
__global__ void __launch_bounds__(256) k_final(const int* __restrict__ spinds,
                                               float* __restrict__ out) {
    __shared__ float sb[TT * MM];
    __shared__ float red[8];
    __shared__ float regsum;
    const int tid = threadIdx.x, lane = tid & 31, warp = tid >> 5;
    if (tid == 0) regsum = 0.f;
    for (int b = 0; b < BB; b++) {
        __syncthreads();
        for (int idx = tid; idx < TT * MM; idx += 256)
            sb[idx] = d_betas[(size_t)b * TT * MM + idx];
        __syncthreads();
        float lsum = 0.f;
        for (int idx = tid; idx < MM * MM; idx += 256) {
            int a = idx / MM, c = idx % MM;
            float v = 0.f;
            for (int t = 0; t < TT; t++)
                v = fmaf(sb[t * MM + a], sb[t * MM + c], v);
            lsum = fmaf(v, v, lsum);
        }
        for (int t = tid; t < TT; t += 256) {
            float v = 0.f;
            for (int m = 0; m < MM; m++)
                v = fmaf(sb[t * MM + m], sb[t * MM + m], v);
            lsum -= v * v;
        }
        #pragma unroll
        for (int off = 16; off; off >>= 1)
            lsum += __shfl_down_sync(0xffffffffu, lsum, off);
        if (lane == 0) red[warp] = lsum;
        __syncthreads();
        if (tid == 0) {
            float s = 0.f;
            for (int w = 0; w < 8; w++) s += red[w];
            regsum += sqrtf(fmaxf(s, 0.f));
        }
    }
    __syncthreads();
    if (tid == 0) {
        float l1 = 0.f, l2 = 0.f;
        for (int a = 0; a < BB; a++) {
            float num = expf(d_S[a * BB + a]);
            float pdq = 0.f, pqd = 0.f;
            for (int k = 0; k < 5; k++) {
                int sp = spinds[a * 5 + k];
                pdq += expf(d_S[a * BB + sp]);
                pqd += expf(d_S[sp * BB + a]);
            }
            l1 += num / pdq;
            l2 += num / pqd;
        }
        out[0] = -(l1 / BB) - (l2 / BB) + regsum / (float)(BB * TT * MM);
    }
}

// ---------------- launcher ----------------
extern "C" void kernel_launch(void* const* d_in, const int* in_sizes, int n_in,
                              void* d_out, int out_size) {
    const float* image  = (const float*)d_in[0];
    const float* text   = (const float*)d_in[1];
    const int*   spinds = (const int*)d_in[3];
    float* out = (float*)d_out;

    k_init<<<576, 256>>>();
    {
        dim3 g(16, MM, BB);
        k_transpose<<<g, 256>>>(image);
    }
    {
        dim3 g(MM, BB);
        k_u<<<g, 256>>>();
    }
    {
        dim3 g((NN + 255) / 256, PP);   // 28 x 64
        k_sim<<<g, 256>>>(text);
    }
    {
        dim3 g(DD / 256, KSPLIT, PP);   // 2 x 4 x 64
        k_gmm<<<g, 256>>>();
    }
    k_score<<<PP, 256>>>(text);
    k_final<<<1, 256>>>(spinds, out);
}

// round 5
// speedup vs baseline: 1.7660x; 1.7660x over previous
#include <cuda_runtime.h>
#include <cuda_bf16.h>
#include <math.h>
#include <stdint.h>

#define BB  8
#define MM  36
#define DD  512
#define HWW 196
#define TT  64
#define NN  7056
#define NNP 7168          // padded N (multiple of 256)
#define PP  64
#define G2  5.0f
#define GSPLIT 4
#define KRANGE (NNP / GSPLIT)   // 1792

// ---------------- scratch (device globals; no allocation) ----------------
__device__ float          d_V[BB * NN * DD];
__device__ __nv_bfloat16  d_Vh[BB * NNP * DD];        // V hi, [b][n][d]
__device__ __nv_bfloat16  d_Vl[BB * NNP * DD];        // V lo
__device__ __nv_bfloat16  d_VhT[BB * DD * NNP];       // V hi transposed, [b][d][n]
__device__ __nv_bfloat16  d_VlT[BB * DD * NNP];
__device__ __nv_bfloat16  d_Eh[BB * TT * DD];
__device__ __nv_bfloat16  d_El[BB * TT * DD];
__device__ __nv_bfloat16  d_W4h[(size_t)PP * TT * NNP];
__device__ __nv_bfloat16  d_W4l[(size_t)PP * TT * NNP];
__device__ float d_Gs[GSPLIT][PP * TT * DD];
__device__ float d_normsq[BB * NN];
__device__ float d_u[BB * MM * DD];
__device__ float d_Zt[PP * TT];
__device__ float d_sExp[PP * TT * MM];
__device__ float d_S[PP];
__device__ float d_betas[BB * TT * MM];

// ---------------- warp MMA helpers (sm_80-era, compile under compute_103) ----
__device__ __forceinline__ uint32_t smem_u32(const void* p) {
    uint32_t a;
    asm("{ .reg .u64 t; cvta.to.shared.u64 t, %1; cvt.u32.u64 %0, t; }"
        : "=r"(a) : "l"(p));
    return a;
}
__device__ __forceinline__ void ldmx4(unsigned* r, uint32_t addr) {
    asm volatile("ldmatrix.sync.aligned.m8n8.x4.shared.b16 {%0,%1,%2,%3}, [%4];"
        : "=r"(r[0]), "=r"(r[1]), "=r"(r[2]), "=r"(r[3]) : "r"(addr));
}
__device__ __forceinline__ void mma_bf16(float* c, const unsigned* a, const unsigned* b) {
    asm volatile("mma.sync.aligned.m16n8k16.row.col.f32.bf16.bf16.f32 "
        "{%0,%1,%2,%3}, {%4,%5,%6,%7}, {%8,%9}, {%0,%1,%2,%3};"
        : "+f"(c[0]), "+f"(c[1]), "+f"(c[2]), "+f"(c[3])
        : "r"(a[0]), "r"(a[1]), "r"(a[2]), "r"(a[3]), "r"(b[0]), "r"(b[1]));
}
__device__ __forceinline__ void bsplit(float v, __nv_bfloat16& h, __nv_bfloat16& l) {
    h = __float2bfloat16(v);
    l = __float2bfloat16(v - __bfloat162float(h));
}

// ---------------- kernel 0: zero accumulators + pad regions ----------------
__global__ void k_init() {
    const int PAD = NNP - NN;   // 112
    int idx0 = blockIdx.x * blockDim.x + threadIdx.x;
    int stride = gridDim.x * blockDim.x;
    const __nv_bfloat16 z = __float2bfloat16(0.f);
    for (int idx = idx0; idx < BB * NN; idx += stride) d_normsq[idx] = 0.f;
    for (int idx = idx0; idx < PP * TT; idx += stride) d_Zt[idx] = 0.f;
    for (int idx = idx0; idx < PP * TT * MM; idx += stride) d_sExp[idx] = 0.f;
    for (int idx = idx0; idx < BB * PAD * DD; idx += stride) {
        int b = idx / (PAD * DD), r = idx % (PAD * DD);
        int n = NN + r / DD, d = r % DD;
        size_t o = ((size_t)b * NNP + n) * DD + d;
        d_Vh[o] = z; d_Vl[o] = z;
        int d2 = r / PAD, n2 = NN + r % PAD;
        size_t o2 = ((size_t)b * DD + d2) * NNP + n2;
        d_VhT[o2] = z; d_VlT[o2] = z;
    }
}

// ---------------- kernel: split text into bf16 hi/lo ----------------
__global__ void k_prep(const float* __restrict__ text) {
    int idx = blockIdx.x * 256 + threadIdx.x;
    if (idx < BB * TT * DD) {
        __nv_bfloat16 h, l;
        bsplit(text[idx], h, l);
        d_Eh[idx] = h; d_El[idx] = l;
    }
}

// ---------------- kernel 1: transpose image -> V (fp32 + bf16 splits) ----------------
__global__ void __launch_bounds__(256) k_transpose(const float* __restrict__ image) {
    __shared__ float tile[32 * 197];
    const int b = blockIdx.z, m = blockIdx.y, d0 = blockIdx.x * 32;
    const float* src = image + ((size_t)(b * MM + m) * DD + d0) * HWW;
    for (int idx = threadIdx.x; idx < 32 * HWW; idx += 256) {
        int dd = idx / HWW, hw = idx % HWW;
        tile[dd * 197 + hw] = src[idx];
    }
    __syncthreads();
    for (int idx = threadIdx.x; idx < HWW * 32; idx += 256) {
        int nl = idx >> 5, dd = idx & 31;
        int w = nl / 14, h = nl % 14;
        float v = tile[dd * 197 + h * 14 + w];
        d_V[((size_t)(b * NN + m * HWW + nl)) * DD + d0 + dd] = v;
        __nv_bfloat16 hi, lo; bsplit(v, hi, lo);
        size_t o = ((size_t)b * NNP + m * HWW + nl) * DD + d0 + dd;
        d_Vh[o] = hi; d_Vl[o] = lo;
    }
    for (int idx = threadIdx.x; idx < 32 * HWW; idx += 256) {
        int dd = idx / HWW, nl = idx % HWW;
        int w = nl / 14, h = nl % 14;
        float v = tile[dd * 197 + h * 14 + w];
        __nv_bfloat16 hi, lo; bsplit(v, hi, lo);
        size_t o = ((size_t)b * DD + d0 + dd) * NNP + m * HWW + nl;
        d_VhT[o] = hi; d_VlT[o] = lo;
    }
    if (threadIdx.x < HWW) {
        int nl = threadIdx.x;
        int w = nl / 14, h = nl % 14;
        float s = 0.f;
        #pragma unroll
        for (int dd = 0; dd < 32; dd++) {
            float v = tile[dd * 197 + h * 14 + w];
            s = fmaf(v, v, s);
        }
        atomicAdd(&d_normsq[b * NN + m * HWW + nl], s);
    }
}

// ---------------- kernel 2: u[b,m,d] = sum_hw V / ||V_row|| ----------------
__global__ void __launch_bounds__(256) k_u() {
    const int m = blockIdx.x, b = blockIdx.y;
    __shared__ float inv[HWW];
    if (threadIdx.x < HWW)
        inv[threadIdx.x] = rsqrtf(d_normsq[b * NN + m * HWW + threadIdx.x]);
    __syncthreads();
    const float* vb = d_V + (size_t)(b * NN + m * HWW) * DD;
    for (int d = threadIdx.x; d < DD; d += 256) {
        float acc = 0.f;
        for (int hw = 0; hw < HWW; hw++)
            acc = fmaf(vb[(size_t)hw * DD + d], inv[hw], acc);
        d_u[(size_t)(b * MM + m) * DD + d] = acc;
    }
}

// ---------------- kernel 3: sim via HMMA (3-term bf16 split) + softmax ----------------
// Block: pair p, 256-n tile. M=64(t) x N=256 x K=512. 8 warps, each 32x64.
__global__ void __launch_bounds__(256) k_sim_mma() {
    extern __shared__ __align__(16) char smem[];
    __nv_bfloat16* sAh = (__nv_bfloat16*)smem;     // [64][40]
    __nv_bfloat16* sAl = sAh + 64 * 40;
    __nv_bfloat16* sBh = sAl + 64 * 40;            // [256][40]
    __nv_bfloat16* sBl = sBh + 256 * 40;
    float* Cs = (float*)smem;                      // epilogue [64][258]
    __shared__ int colm[256];
    __shared__ float psum[64][4][4];

    const int tid = threadIdx.x, lane = tid & 31, wid = tid >> 5;
    const int p = blockIdx.y, i = p >> 3, j = p & 7;
    const int n0 = blockIdx.x * 256;
    const int wm = (wid >> 2) * 32, wn = (wid & 3) * 64;

    float C[2][8][4];
    #pragma unroll
    for (int mi = 0; mi < 2; mi++)
        #pragma unroll
        for (int nj = 0; nj < 8; nj++)
            #pragma unroll
            for (int k = 0; k < 4; k++) C[mi][nj][k] = 0.f;

    const int lg = lane >> 3;
    const int arow = (lane & 7) + (lg & 1) * 8, akoff = (lg >> 1) * 8;
    const int brow = (lane & 7) + (lg >> 1) * 8, bkoff = (lg & 1) * 8;

    for (int k0 = 0; k0 < DD; k0 += 32) {
        {
            int row = tid >> 2, q = tid & 3;
            size_t so = ((size_t)j * TT + row) * DD + k0 + q * 8;
            *(uint4*)&sAh[row * 40 + q * 8] = *(const uint4*)&d_Eh[so];
            *(uint4*)&sAl[row * 40 + q * 8] = *(const uint4*)&d_El[so];
        }
        #pragma unroll
        for (int r = 0; r < 4; r++) {
            int idx = tid + r * 256;
            int row = idx >> 2, q = idx & 3;
            size_t so = ((size_t)i * NNP + n0 + row) * DD + k0 + q * 8;
            *(uint4*)&sBh[row * 40 + q * 8] = *(const uint4*)&d_Vh[so];
            *(uint4*)&sBl[row * 40 + q * 8] = *(const uint4*)&d_Vl[so];
        }
        __syncthreads();
        #pragma unroll
        for (int ks = 0; ks < 32; ks += 16) {
            unsigned ah[2][4], al[2][4], bf[8][2];
            #pragma unroll
            for (int mi = 0; mi < 2; mi++) {
                int rb = (wm + mi * 16 + arow) * 40 + ks + akoff;
                ldmx4(ah[mi], smem_u32(sAh + rb));
                ldmx4(al[mi], smem_u32(sAl + rb));
            }
            #pragma unroll
            for (int bi = 0; bi < 4; bi++) {
                unsigned r[4];
                ldmx4(r, smem_u32(sBh + (wn + bi * 16 + brow) * 40 + ks + bkoff));
                bf[2 * bi][0] = r[0]; bf[2 * bi][1] = r[1];
                bf[2 * bi + 1][0] = r[2]; bf[2 * bi + 1][1] = r[3];
            }
            #pragma unroll
            for (int mi = 0; mi < 2; mi++)
                #pragma unroll
                for (int nj = 0; nj < 8; nj++) mma_bf16(C[mi][nj], ah[mi], bf[nj]);
            #pragma unroll
            for (int mi = 0; mi < 2; mi++)
                #pragma unroll
                for (int nj = 0; nj < 8; nj++) mma_bf16(C[mi][nj], al[mi], bf[nj]);
            #pragma unroll
            for (int bi = 0; bi < 4; bi++) {
                unsigned r[4];
                ldmx4(r, smem_u32(sBl + (wn + bi * 16 + brow) * 40 + ks + bkoff));
                bf[2 * bi][0] = r[0]; bf[2 * bi][1] = r[1];
                bf[2 * bi + 1][0] = r[2]; bf[2 * bi + 1][1] = r[3];
            }
            #pragma unroll
            for (int mi = 0; mi < 2; mi++)
                #pragma unroll
                for (int nj = 0; nj < 8; nj++) mma_bf16(C[mi][nj], ah[mi], bf[nj]);
        }
        __syncthreads();
    }

    // ---------------- epilogue ----------------
    #pragma unroll
    for (int mi = 0; mi < 2; mi++)
        #pragma unroll
        for (int nj = 0; nj < 8; nj++) {
            int row = wm + mi * 16 + (lane >> 2);
            int col = wn + nj * 8 + (lane & 3) * 2;
            *(float2*)&Cs[row * 258 + col] = make_float2(C[mi][nj][0], C[mi][nj][1]);
            *(float2*)&Cs[(row + 8) * 258 + col] = make_float2(C[mi][nj][2], C[mi][nj][3]);
        }
    colm[tid] = (n0 + tid < NN) ? (n0 + tid) / HWW : -1;
    __syncthreads();

    {   // column softmax over t, write W4 hi/lo (pads included, stats excluded)
        const int col = tid;
        float mx = -1e30f;
        for (int t = 0; t < TT; t++) mx = fmaxf(mx, Cs[t * 258 + col]);
        float s = 0.f;
        for (int t = 0; t < TT; t++) {
            float e = __expf(Cs[t * 258 + col] - mx);
            s += e;
            Cs[t * 258 + col] = e;
        }
        float inv = 1.f / s;
        __nv_bfloat16* wh = d_W4h + (size_t)p * TT * NNP + n0 + col;
        __nv_bfloat16* wl = d_W4l + (size_t)p * TT * NNP + n0 + col;
        for (int t = 0; t < TT; t++) {
            float ns = Cs[t * 258 + col] * inv;
            float en = __expf(ns);
            Cs[t * 258 + col] = en;
            float e4 = en * en; e4 *= e4;
            __nv_bfloat16 h, l; bsplit(e4, h, l);
            wh[(size_t)t * NNP] = h;
            wl[(size_t)t * NNP] = l;
        }
    }
    __syncthreads();
    {
        const int t = tid >> 2, qc = tid & 3;
        const int m_base = n0 / HWW;
        float z = 0.f, s0 = 0.f, s1 = 0.f, s2 = 0.f;
        for (int c = qc * 64; c < qc * 64 + 64; c++) {
            int bm = colm[c];
            if (bm >= 0) {
                float en = Cs[t * 258 + c];
                float e4 = en * en; e4 *= e4;
                z += e4;
                int sel = bm - m_base;
                if (sel == 0) s0 += en; else if (sel == 1) s1 += en; else s2 += en;
            }
        }
        psum[t][qc][0] = z; psum[t][qc][1] = s0;
        psum[t][qc][2] = s1; psum[t][qc][3] = s2;
    }
    __syncthreads();
    if (tid < TT) {
        float z = 0.f, s0 = 0.f, s1 = 0.f, s2 = 0.f;
        #pragma unroll
        for (int qc = 0; qc < 4; qc++) {
            z += psum[tid][qc][0]; s0 += psum[tid][qc][1];
            s1 += psum[tid][qc][2]; s2 += psum[tid][qc][3];
        }
        const int m_base = n0 / HWW;
        atomicAdd(&d_Zt[p * TT + tid], z);
        atomicAdd(&d_sExp[((size_t)p * TT + tid) * MM + m_base], s0);
        if (m_base + 1 < MM && s1 != 0.f)
            atomicAdd(&d_sExp[((size_t)p * TT + tid) * MM + m_base + 1], s1);
        if (m_base + 2 < MM && s2 != 0.f)
            atomicAdd(&d_sExp[((size_t)p * TT + tid) * MM + m_base + 2], s2);
    }
}

// ---------------- kernel 4: Gs[s][p,t,d] via HMMA ----------------
// Block: pair p, 128-d tile, 1/4 of n. M=64(t) x N=128(d) x K=1792. 8 warps 32x32.
__global__ void __launch_bounds__(256) k_gmm_mma() {
    __shared__ __align__(16) __nv_bfloat16 sAh[64 * 40], sAl[64 * 40];
    __shared__ __align__(16) __nv_bfloat16 sBh[128 * 40], sBl[128 * 40];

    const int tid = threadIdx.x, lane = tid & 31, wid = tid >> 5;
    const int p = blockIdx.z, i = p >> 3;
    const int d0 = blockIdx.x * 128;
    const int s = blockIdx.y;
    const int kbase = s * KRANGE;
    const int wm = (wid >> 2) * 32, wn = (wid & 3) * 32;

    float C[2][4][4];
    #pragma unroll
    for (int mi = 0; mi < 2; mi++)
        #pragma unroll
        for (int nj = 0; nj < 4; nj++)
            #pragma unroll
            for (int k = 0; k < 4; k++) C[mi][nj][k] = 0.f;

    const int lg = lane >> 3;
    const int arow = (lane & 7) + (lg & 1) * 8, akoff = (lg >> 1) * 8;
    const int brow = (lane & 7) + (lg >> 1) * 8, bkoff = (lg & 1) * 8;

    for (int kc = 0; kc < KRANGE; kc += 32) {
        const int kb = kbase + kc;
        {
            int row = tid >> 2, q = tid & 3;
            size_t ao = ((size_t)p * TT + row) * NNP + kb + q * 8;
            *(uint4*)&sAh[row * 40 + q * 8] = *(const uint4*)&d_W4h[ao];
            *(uint4*)&sAl[row * 40 + q * 8] = *(const uint4*)&d_W4l[ao];
        }
        #pragma unroll
        for (int r = 0; r < 2; r++) {
            int idx = tid + r * 256;
            int row = idx >> 2, q = idx & 3;
            size_t bo = ((size_t)i * DD + d0 + row) * NNP + kb + q * 8;
            *(uint4*)&sBh[row * 40 + q * 8] = *(const uint4*)&d_VhT[bo];
            *(uint4*)&sBl[row * 40 + q * 8] = *(const uint4*)&d_VlT[bo];
        }
        __syncthreads();
        #pragma unroll
        for (int ks = 0; ks < 32; ks += 16) {
            unsigned ah[2][4], al[2][4], bf[4][2];
            #pragma unroll
            for (int mi = 0; mi < 2; mi++) {
                int rb = (wm + mi * 16 + arow) * 40 + ks + akoff;
                ldmx4(ah[mi], smem_u32(sAh + rb));
                ldmx4(al[mi], smem_u32(sAl + rb));
            }
            #pragma unroll
            for (int bi = 0; bi < 2; bi++) {
                unsigned r[4];
                ldmx4(r, smem_u32(sBh + (wn + bi * 16 + brow) * 40 + ks + bkoff));
                bf[2 * bi][0] = r[0]; bf[2 * bi][1] = r[1];
                bf[2 * bi + 1][0] = r[2]; bf[2 * bi + 1][1] = r[3];
            }
            #pragma unroll
            for (int mi = 0; mi < 2; mi++)
                #pragma unroll
                for (int nj = 0; nj < 4; nj++) mma_bf16(C[mi][nj], ah[mi], bf[nj]);
            #pragma unroll
            for (int mi = 0; mi < 2; mi++)
                #pragma unroll
                for (int nj = 0; nj < 4; nj++) mma_bf16(C[mi][nj], al[mi], bf[nj]);
            #pragma unroll
            for (int bi = 0; bi < 2; bi++) {
                unsigned r[4];
                ldmx4(r, smem_u32(sBl + (wn + bi * 16 + brow) * 40 + ks + bkoff));
                bf[2 * bi][0] = r[0]; bf[2 * bi][1] = r[1];
                bf[2 * bi + 1][0] = r[2]; bf[2 * bi + 1][1] = r[3];
            }
            #pragma unroll
            for (int mi = 0; mi < 2; mi++)
                #pragma unroll
                for (int nj = 0; nj < 4; nj++) mma_bf16(C[mi][nj], ah[mi], bf[nj]);
        }
        __syncthreads();
    }

    float* Gp = &d_Gs[s][((size_t)p * TT) * DD + d0];
    #pragma unroll
    for (int mi = 0; mi < 2; mi++)
        #pragma unroll
        for (int nj = 0; nj < 4; nj++) {
            int row = wm + mi * 16 + (lane >> 2);
            int col = wn + nj * 8 + (lane & 3) * 2;
            *(float2*)&Gp[(size_t)row * DD + col] = make_float2(C[mi][nj][0], C[mi][nj][1]);
            *(float2*)&Gp[(size_t)(row + 8) * DD + col] = make_float2(C[mi][nj][2], C[mi][nj][3]);
        }
}

// ---------------- kernel 5: per-pair score S[p] ----------------
__global__ void __launch_bounds__(256) k_score(const float* __restrict__ text) {
    const int p = blockIdx.x, i = p >> 3, j = p & 7;
    __shared__ float sbeta[TT * MM];
    __shared__ float sls[MM];
    __shared__ float sdiag[TT];
    __shared__ float snrm[MM], sdot[MM];
    __shared__ float Es[TT * 128];
    const int tid = threadIdx.x, lane = tid & 31, warp = tid >> 5;
    const float* E = text + (size_t)j * TT * DD;

    for (int idx = tid; idx < TT * MM; idx += 256)
        sbeta[idx] = d_sExp[(size_t)p * TT * MM + idx];
    if (tid < MM) { snrm[tid] = 0.f; sdot[tid] = 0.f; }
    __syncthreads();
    if (tid < MM) {
        float s = 0.f;
        for (int t = 0; t < TT; t++) s += sbeta[t * MM + tid];
        sls[tid] = 1.0f / s;
    }
    __syncthreads();
    for (int idx = tid; idx < TT * MM; idx += 256) {
        float v = sbeta[idx] * sls[idx % MM];
        sbeta[idx] = v;
        if (i == j) d_betas[(size_t)i * TT * MM + idx] = v;
    }
    __syncthreads();

    for (int t = warp; t < TT; t += 8) {
        const size_t off = ((size_t)p * TT + t) * DD;
        const float* Er = E + (size_t)t * DD;
        float s = 0.f;
        for (int d = lane; d < DD; d += 32) {
            float g = d_Gs[0][off + d] + d_Gs[1][off + d]
                    + d_Gs[2][off + d] + d_Gs[3][off + d];
            s = fmaf(g, Er[d], s);
        }
        #pragma unroll
        for (int o = 16; o; o >>= 1) s += __shfl_down_sync(0xffffffffu, s, o);
        if (lane == 0) sdiag[t] = s / d_Zt[p * TT + t];
    }

    const float* U = d_u + (size_t)i * MM * DD;
    const int grp = tid >> 7;
    const int dl = tid & 127;
    for (int d0 = 0; d0 < DD; d0 += 128) {
        __syncthreads();
        for (int idx = tid; idx < TT * 128; idx += 256) {
            int t = idx >> 7, dloc = idx & 127;
            Es[idx] = E[(size_t)t * DD + d0 + dloc];
        }
        __syncthreads();
        for (int m = grp; m < MM; m += 2) {
            float v = 0.f;
            #pragma unroll 16
            for (int t = 0; t < TT; t++)
                v = fmaf(sbeta[t * MM + m], Es[t * 128 + dl], v);
            float nr = v * v;
            float dt = v * U[(size_t)m * DD + d0 + dl];
            #pragma unroll
            for (int o = 16; o; o >>= 1) {
                nr += __shfl_down_sync(0xffffffffu, nr, o);
                dt += __shfl_down_sync(0xffffffffu, dt, o);
            }
            if (lane == 0) { atomicAdd(&snrm[m], nr); atomicAdd(&sdot[m], dt); }
        }
    }
    __syncthreads();
    if (tid == 0) {
        float se = 0.f;
        for (int t = 0; t < TT; t++) se += expf(G2 * sdiag[t]);
        float r_qd = (1.0f / G2) * logf(se);
        float sm = 0.f;
        for (int m = 0; m < MM; m++)
            sm += expf(sdot[m] / ((float)HWW * sqrtf(snrm[m])));
        d_S[p] = r_qd + (1.0f / G2) * logf(sm);
    }
}

// ---------------- kernel 6: final scalar ----------------
__global__ void __launch_bounds__(256) k_final(const int* __restrict__ spinds,
                                               float* __restrict__ out) {
    __shared__ float sbm[TT * MM];
    __shared__ float red[8];
    __shared__ float regsum;
    const int tid = threadIdx.x, lane = tid & 31, warp = tid >> 5;
    if (tid == 0) regsum = 0.f;
    for (int b = 0; b < BB; b++) {
        __syncthreads();
        for (int idx = tid; idx < TT * MM; idx += 256)
            sbm[idx] = d_betas[(size_t)b * TT * MM + idx];
        __syncthreads();
        float lsum = 0.f;
        for (int idx = tid; idx < MM * MM; idx += 256) {
            int a = idx / MM, c = idx % MM;
            float v = 0.f;
            for (int t = 0; t < TT; t++)
                v = fmaf(sbm[t * MM + a], sbm[t * MM + c], v);
            lsum = fmaf(v, v, lsum);
        }
        for (int t = tid; t < TT; t += 256) {
            float v = 0.f;
            for (int m = 0; m < MM; m++)
                v = fmaf(sbm[t * MM + m], sbm[t * MM + m], v);
            lsum -= v * v;
        }
        #pragma unroll
        for (int o = 16; o; o >>= 1)
            lsum += __shfl_down_sync(0xffffffffu, lsum, o);
        if (lane == 0) red[warp] = lsum;
        __syncthreads();
        if (tid == 0) {
            float s = 0.f;
            for (int w = 0; w < 8; w++) s += red[w];
            regsum += sqrtf(fmaxf(s, 0.f));
        }
    }
    __syncthreads();
    if (tid == 0) {
        float l1 = 0.f, l2 = 0.f;
        for (int a = 0; a < BB; a++) {
            float num = expf(d_S[a * BB + a]);
            float pdq = 0.f, pqd = 0.f;
            for (int k = 0; k < 5; k++) {
                int sp = spinds[a * 5 + k];
                pdq += expf(d_S[a * BB + sp]);
                pqd += expf(d_S[sp * BB + a]);
            }
            l1 += num / pdq;
            l2 += num / pqd;
        }
        out[0] = -(l1 / BB) - (l2 / BB) + regsum / (float)(BB * TT * MM);
    }
}

// ---------------- launcher ----------------
#define SMEM_SIM (64 * 258 * 4)   // 66048 bytes (epilogue Cs dominates)

extern "C" void kernel_launch(void* const* d_in, const int* in_sizes, int n_in,
                              void* d_out, int out_size) {
    const float* image  = (const float*)d_in[0];
    const float* text   = (const float*)d_in[1];
    const int*   spinds = (const int*)d_in[3];
    float* out = (float*)d_out;

    cudaFuncSetAttribute(k_sim_mma, cudaFuncAttributeMaxDynamicSharedMemorySize, SMEM_SIM);

    k_init<<<1024, 256>>>();
    k_prep<<<(BB * TT * DD) / 256, 256>>>(text);
    {
        dim3 g(16, MM, BB);
        k_transpose<<<g, 256>>>(image);
    }
    {
        dim3 g(MM, BB);
        k_u<<<g, 256>>>();
    }
    {
        dim3 g(NNP / 256, PP);          // 28 x 64
        k_sim_mma<<<g, 256, SMEM_SIM>>>();
    }
    {
        dim3 g(DD / 128, GSPLIT, PP);   // 4 x 4 x 64
        k_gmm_mma<<<g, 256>>>();
    }
    k_score<<<PP, 256>>>(text);
    k_final<<<1, 256>>>(spinds, out);
}

// round 6
// speedup vs baseline: 1.8961x; 1.0736x over previous
#include <cuda_runtime.h>
#include <cuda_bf16.h>
#include <math.h>
#include <stdint.h>

#define BB  8
#define MM  36
#define DD  512
#define HWW 196
#define TT  64
#define NN  7056
#define NNP 7168          // padded N (multiple of 256)
#define PP  64
#define G2  5.0f
#define GSPLIT 4
#define KRANGE (NNP / GSPLIT)   // 1792

// ---------------- scratch (device globals; no allocation) ----------------
__device__ float          d_V[BB * NN * DD];
__device__ __nv_bfloat16  d_Vh[BB * NNP * DD];        // V hi, [b][n][d]
__device__ __nv_bfloat16  d_Vl[BB * NNP * DD];        // V lo
__device__ __nv_bfloat16  d_VhT[BB * DD * NNP];       // V hi transposed, [b][d][n]
__device__ __nv_bfloat16  d_VlT[BB * DD * NNP];
__device__ __nv_bfloat16  d_Eh[BB * TT * DD];
__device__ __nv_bfloat16  d_El[BB * TT * DD];
__device__ __nv_bfloat16  d_W4h[(size_t)PP * TT * NNP];
__device__ __nv_bfloat16  d_W4l[(size_t)PP * TT * NNP];
__device__ float d_Gs[GSPLIT][PP * TT * DD];
__device__ float d_normsq[BB * NN];
__device__ float d_u[BB * MM * DD];
__device__ float d_Zt[PP * TT];
__device__ float d_sExp[PP * TT * MM];
__device__ float d_S[PP];
__device__ float d_betas[BB * TT * MM];

// ---------------- warp MMA + cp.async helpers ----------------
__device__ __forceinline__ uint32_t smem_u32(const void* p) {
    uint32_t a;
    asm("{ .reg .u64 t; cvta.to.shared.u64 t, %1; cvt.u32.u64 %0, t; }"
        : "=r"(a) : "l"(p));
    return a;
}
__device__ __forceinline__ void ldmx4(unsigned* r, uint32_t addr) {
    asm volatile("ldmatrix.sync.aligned.m8n8.x4.shared.b16 {%0,%1,%2,%3}, [%4];"
        : "=r"(r[0]), "=r"(r[1]), "=r"(r[2]), "=r"(r[3]) : "r"(addr));
}
__device__ __forceinline__ void mma_bf16(float* c, const unsigned* a, const unsigned* b) {
    asm volatile("mma.sync.aligned.m16n8k16.row.col.f32.bf16.bf16.f32 "
        "{%0,%1,%2,%3}, {%4,%5,%6,%7}, {%8,%9}, {%0,%1,%2,%3};"
        : "+f"(c[0]), "+f"(c[1]), "+f"(c[2]), "+f"(c[3])
        : "r"(a[0]), "r"(a[1]), "r"(a[2]), "r"(a[3]), "r"(b[0]), "r"(b[1]));
}
__device__ __forceinline__ void cpa16(uint32_t dst, const void* src) {
    asm volatile("cp.async.ca.shared.global [%0], [%1], 16;"
        :: "r"(dst), "l"(src) : "memory");
}
#define CP_COMMIT() asm volatile("cp.async.commit_group;" ::: "memory")
#define CP_WAIT1()  asm volatile("cp.async.wait_group 1;" ::: "memory")
__device__ __forceinline__ void bsplit(float v, __nv_bfloat16& h, __nv_bfloat16& l) {
    h = __float2bfloat16(v);
    l = __float2bfloat16(v - __bfloat162float(h));
}

// stage layout (bf16 elems): Ah[64*40], Al[64*40], Bh[256*40], Bl[256*40]
#define OFF_AL (64 * 40)
#define OFF_BH (128 * 40)
#define OFF_BL (128 * 40 + 256 * 40)
#define STAGE_ELEMS (128 * 40 + 512 * 40)   // 25600 elems = 51200 B
#define SMEM_DYN (2 * STAGE_ELEMS * 2)      // 102400 B

// ---------------- kernel 0: zero accumulators + pad regions ----------------
__global__ void k_init() {
    const int PAD = NNP - NN;   // 112
    int idx0 = blockIdx.x * blockDim.x + threadIdx.x;
    int stride = gridDim.x * blockDim.x;
    const __nv_bfloat16 z = __float2bfloat16(0.f);
    for (int idx = idx0; idx < BB * NN; idx += stride) d_normsq[idx] = 0.f;
    for (int idx = idx0; idx < PP * TT; idx += stride) d_Zt[idx] = 0.f;
    for (int idx = idx0; idx < PP * TT * MM; idx += stride) d_sExp[idx] = 0.f;
    for (int idx = idx0; idx < BB * PAD * DD; idx += stride) {
        int b = idx / (PAD * DD), r = idx % (PAD * DD);
        int n = NN + r / DD, d = r % DD;
        size_t o = ((size_t)b * NNP + n) * DD + d;
        d_Vh[o] = z; d_Vl[o] = z;
        int d2 = r / PAD, n2 = NN + r % PAD;
        size_t o2 = ((size_t)b * DD + d2) * NNP + n2;
        d_VhT[o2] = z; d_VlT[o2] = z;
    }
}

// ---------------- kernel: split text into bf16 hi/lo ----------------
__global__ void k_prep(const float* __restrict__ text) {
    int idx = blockIdx.x * 256 + threadIdx.x;
    if (idx < BB * TT * DD) {
        __nv_bfloat16 h, l;
        bsplit(text[idx], h, l);
        d_Eh[idx] = h; d_El[idx] = l;
    }
}

// ---------------- kernel 1: transpose image -> V (fp32 + bf16 splits) ----------------
__global__ void __launch_bounds__(256) k_transpose(const float* __restrict__ image) {
    __shared__ float tile[32 * 197];
    const int b = blockIdx.z, m = blockIdx.y, d0 = blockIdx.x * 32;
    const float* src = image + ((size_t)(b * MM + m) * DD + d0) * HWW;
    for (int idx = threadIdx.x; idx < 32 * HWW; idx += 256) {
        int dd = idx / HWW, hw = idx % HWW;
        tile[dd * 197 + hw] = src[idx];
    }
    __syncthreads();
    for (int idx = threadIdx.x; idx < HWW * 32; idx += 256) {
        int nl = idx >> 5, dd = idx & 31;
        int w = nl / 14, h = nl % 14;
        float v = tile[dd * 197 + h * 14 + w];
        d_V[((size_t)(b * NN + m * HWW + nl)) * DD + d0 + dd] = v;
        __nv_bfloat16 hi, lo; bsplit(v, hi, lo);
        size_t o = ((size_t)b * NNP + m * HWW + nl) * DD + d0 + dd;
        d_Vh[o] = hi; d_Vl[o] = lo;
    }
    for (int idx = threadIdx.x; idx < 32 * HWW; idx += 256) {
        int dd = idx / HWW, nl = idx % HWW;
        int w = nl / 14, h = nl % 14;
        float v = tile[dd * 197 + h * 14 + w];
        __nv_bfloat16 hi, lo; bsplit(v, hi, lo);
        size_t o = ((size_t)b * DD + d0 + dd) * NNP + m * HWW + nl;
        d_VhT[o] = hi; d_VlT[o] = lo;
    }
    if (threadIdx.x < HWW) {
        int nl = threadIdx.x;
        int w = nl / 14, h = nl % 14;
        float s = 0.f;
        #pragma unroll
        for (int dd = 0; dd < 32; dd++) {
            float v = tile[dd * 197 + h * 14 + w];
            s = fmaf(v, v, s);
        }
        atomicAdd(&d_normsq[b * NN + m * HWW + nl], s);
    }
}

// ---------------- kernel 2: u[b,m,d] = sum_hw V / ||V_row|| ----------------
__global__ void __launch_bounds__(256) k_u() {
    const int m = blockIdx.x, b = blockIdx.y;
    __shared__ float inv[HWW];
    if (threadIdx.x < HWW)
        inv[threadIdx.x] = rsqrtf(d_normsq[b * NN + m * HWW + threadIdx.x]);
    __syncthreads();
    const float* vb = d_V + (size_t)(b * NN + m * HWW) * DD;
    for (int d = threadIdx.x; d < DD; d += 256) {
        float acc = 0.f;
        for (int hw = 0; hw < HWW; hw++)
            acc = fmaf(vb[(size_t)hw * DD + d], inv[hw], acc);
        d_u[(size_t)(b * MM + m) * DD + d] = acc;
    }
}

// ---------------- shared MMA mainloop body (64 x 256 tile, 8 warps) ----------------
// Computes C[2][8][4] += 3-term split product of A(64xK) and B(256xK) chunks.
struct Frag { float C[2][8][4]; };

__device__ __forceinline__ void mma_chunk(__nv_bfloat16* stage, int wm, int wn,
                                          int arow, int akoff, int brow, int bkoff,
                                          Frag& f) {
    __nv_bfloat16* sAh = stage;
    __nv_bfloat16* sAl = stage + OFF_AL;
    __nv_bfloat16* sBh = stage + OFF_BH;
    __nv_bfloat16* sBl = stage + OFF_BL;
    #pragma unroll
    for (int ks = 0; ks < 32; ks += 16) {
        unsigned ah[2][4], al[2][4], bf[8][2];
        #pragma unroll
        for (int mi = 0; mi < 2; mi++) {
            int rb = (wm + mi * 16 + arow) * 40 + ks + akoff;
            ldmx4(ah[mi], smem_u32(sAh + rb));
            ldmx4(al[mi], smem_u32(sAl + rb));
        }
        #pragma unroll
        for (int bi = 0; bi < 4; bi++) {
            unsigned r[4];
            ldmx4(r, smem_u32(sBh + (wn + bi * 16 + brow) * 40 + ks + bkoff));
            bf[2 * bi][0] = r[0]; bf[2 * bi][1] = r[1];
            bf[2 * bi + 1][0] = r[2]; bf[2 * bi + 1][1] = r[3];
        }
        #pragma unroll
        for (int mi = 0; mi < 2; mi++)
            #pragma unroll
            for (int nj = 0; nj < 8; nj++) mma_bf16(f.C[mi][nj], ah[mi], bf[nj]);
        #pragma unroll
        for (int mi = 0; mi < 2; mi++)
            #pragma unroll
            for (int nj = 0; nj < 8; nj++) mma_bf16(f.C[mi][nj], al[mi], bf[nj]);
        #pragma unroll
        for (int bi = 0; bi < 4; bi++) {
            unsigned r[4];
            ldmx4(r, smem_u32(sBl + (wn + bi * 16 + brow) * 40 + ks + bkoff));
            bf[2 * bi][0] = r[0]; bf[2 * bi][1] = r[1];
            bf[2 * bi + 1][0] = r[2]; bf[2 * bi + 1][1] = r[3];
        }
        #pragma unroll
        for (int mi = 0; mi < 2; mi++)
            #pragma unroll
            for (int nj = 0; nj < 8; nj++) mma_bf16(f.C[mi][nj], ah[mi], bf[nj]);
    }
}

// ---------------- kernel 3: sim via HMMA + cp.async pipeline + softmax ----------------
__global__ void __launch_bounds__(256) k_sim_mma() {
    extern __shared__ __align__(16) char smem[];
    __shared__ int colm[256];
    __shared__ float psum[64][4][4];
    float* Cs = (float*)smem;                       // epilogue [64][258]

    const int tid = threadIdx.x, lane = tid & 31, wid = tid >> 5;
    const int p = blockIdx.y, i = p >> 3, j = p & 7;
    const int n0 = blockIdx.x * 256;
    const int wm = (wid >> 2) * 32, wn = (wid & 3) * 64;

    Frag f;
    #pragma unroll
    for (int mi = 0; mi < 2; mi++)
        #pragma unroll
        for (int nj = 0; nj < 8; nj++)
            #pragma unroll
            for (int k = 0; k < 4; k++) f.C[mi][nj][k] = 0.f;

    const int lg = lane >> 3;
    const int arow = (lane & 7) + (lg & 1) * 8, akoff = (lg >> 1) * 8;
    const int brow = (lane & 7) + (lg >> 1) * 8, bkoff = (lg & 1) * 8;

    const int lrow = tid >> 2, lq = tid & 3;
    auto load_chunk = [&](int st, int k0) {
        __nv_bfloat16* stage = (__nv_bfloat16*)smem + st * STAGE_ELEMS;
        size_t ao = ((size_t)j * TT + lrow) * DD + k0 + lq * 8;
        cpa16(smem_u32(stage + lrow * 40 + lq * 8), d_Eh + ao);
        cpa16(smem_u32(stage + OFF_AL + lrow * 40 + lq * 8), d_El + ao);
        #pragma unroll
        for (int r = 0; r < 4; r++) {
            int idx = tid + r * 256;
            int row = idx >> 2, q = idx & 3;
            size_t vo = ((size_t)i * NNP + n0 + row) * DD + k0 + q * 8;
            cpa16(smem_u32(stage + OFF_BH + row * 40 + q * 8), d_Vh + vo);
            cpa16(smem_u32(stage + OFF_BL + row * 40 + q * 8), d_Vl + vo);
        }
    };

    load_chunk(0, 0);
    CP_COMMIT();
    const int NCH = DD / 32;   // 16
    for (int ch = 0; ch < NCH; ch++) {
        if (ch + 1 < NCH) load_chunk((ch + 1) & 1, (ch + 1) * 32);
        CP_COMMIT();
        CP_WAIT1();
        __syncthreads();
        mma_chunk((__nv_bfloat16*)smem + (ch & 1) * STAGE_ELEMS,
                  wm, wn, arow, akoff, brow, bkoff, f);
        __syncthreads();
    }

    // ---------------- epilogue ----------------
    #pragma unroll
    for (int mi = 0; mi < 2; mi++)
        #pragma unroll
        for (int nj = 0; nj < 8; nj++) {
            int row = wm + mi * 16 + (lane >> 2);
            int col = wn + nj * 8 + (lane & 3) * 2;
            *(float2*)&Cs[row * 258 + col] = make_float2(f.C[mi][nj][0], f.C[mi][nj][1]);
            *(float2*)&Cs[(row + 8) * 258 + col] = make_float2(f.C[mi][nj][2], f.C[mi][nj][3]);
        }
    colm[tid] = (n0 + tid < NN) ? (n0 + tid) / HWW : -1;
    __syncthreads();

    {   // column softmax over t, write W4 hi/lo
        const int col = tid;
        float mx = -1e30f;
        for (int t = 0; t < TT; t++) mx = fmaxf(mx, Cs[t * 258 + col]);
        float s = 0.f;
        for (int t = 0; t < TT; t++) {
            float e = __expf(Cs[t * 258 + col] - mx);
            s += e;
            Cs[t * 258 + col] = e;
        }
        float inv = 1.f / s;
        __nv_bfloat16* wh = d_W4h + (size_t)p * TT * NNP + n0 + col;
        __nv_bfloat16* wl = d_W4l + (size_t)p * TT * NNP + n0 + col;
        for (int t = 0; t < TT; t++) {
            float ns = Cs[t * 258 + col] * inv;
            float en = __expf(ns);
            Cs[t * 258 + col] = en;
            float e4 = en * en; e4 *= e4;
            __nv_bfloat16 h, l; bsplit(e4, h, l);
            wh[(size_t)t * NNP] = h;
            wl[(size_t)t * NNP] = l;
        }
    }
    __syncthreads();
    {
        const int t = tid >> 2, qc = tid & 3;
        const int m_base = n0 / HWW;
        float z = 0.f, s0 = 0.f, s1 = 0.f, s2 = 0.f;
        for (int c = qc * 64; c < qc * 64 + 64; c++) {
            int bm = colm[c];
            if (bm >= 0) {
                float en = Cs[t * 258 + c];
                float e4 = en * en; e4 *= e4;
                z += e4;
                int sel = bm - m_base;
                if (sel == 0) s0 += en; else if (sel == 1) s1 += en; else s2 += en;
            }
        }
        psum[t][qc][0] = z; psum[t][qc][1] = s0;
        psum[t][qc][2] = s1; psum[t][qc][3] = s2;
    }
    __syncthreads();
    if (tid < TT) {
        float z = 0.f, s0 = 0.f, s1 = 0.f, s2 = 0.f;
        #pragma unroll
        for (int qc = 0; qc < 4; qc++) {
            z += psum[tid][qc][0]; s0 += psum[tid][qc][1];
            s1 += psum[tid][qc][2]; s2 += psum[tid][qc][3];
        }
        const int m_base = n0 / HWW;
        atomicAdd(&d_Zt[p * TT + tid], z);
        atomicAdd(&d_sExp[((size_t)p * TT + tid) * MM + m_base], s0);
        if (m_base + 1 < MM && s1 != 0.f)
            atomicAdd(&d_sExp[((size_t)p * TT + tid) * MM + m_base + 1], s1);
        if (m_base + 2 < MM && s2 != 0.f)
            atomicAdd(&d_sExp[((size_t)p * TT + tid) * MM + m_base + 2], s2);
    }
}

// ---------------- kernel 4: Gs[s][p,t,d] via HMMA + cp.async, N=256 ----------------
__global__ void __launch_bounds__(256) k_gmm_mma() {
    extern __shared__ __align__(16) char smem[];
    const int tid = threadIdx.x, lane = tid & 31, wid = tid >> 5;
    const int p = blockIdx.z, i = p >> 3;
    const int d0 = blockIdx.x * 256;
    const int s = blockIdx.y;
    const int kbase = s * KRANGE;
    const int wm = (wid >> 2) * 32, wn = (wid & 3) * 64;

    Frag f;
    #pragma unroll
    for (int mi = 0; mi < 2; mi++)
        #pragma unroll
        for (int nj = 0; nj < 8; nj++)
            #pragma unroll
            for (int k = 0; k < 4; k++) f.C[mi][nj][k] = 0.f;

    const int lg = lane >> 3;
    const int arow = (lane & 7) + (lg & 1) * 8, akoff = (lg >> 1) * 8;
    const int brow = (lane & 7) + (lg >> 1) * 8, bkoff = (lg & 1) * 8;

    const int lrow = tid >> 2, lq = tid & 3;
    auto load_chunk = [&](int st, int kb) {
        __nv_bfloat16* stage = (__nv_bfloat16*)smem + st * STAGE_ELEMS;
        size_t ao = ((size_t)p * TT + lrow) * NNP + kb + lq * 8;
        cpa16(smem_u32(stage + lrow * 40 + lq * 8), d_W4h + ao);
        cpa16(smem_u32(stage + OFF_AL + lrow * 40 + lq * 8), d_W4l + ao);
        #pragma unroll
        for (int r = 0; r < 4; r++) {
            int idx = tid + r * 256;
            int row = idx >> 2, q = idx & 3;
            size_t bo = ((size_t)i * DD + d0 + row) * NNP + kb + q * 8;
            cpa16(smem_u32(stage + OFF_BH + row * 40 + q * 8), d_VhT + bo);
            cpa16(smem_u32(stage + OFF_BL + row * 40 + q * 8), d_VlT + bo);
        }
    };

    load_chunk(0, kbase);
    CP_COMMIT();
    const int NCH = KRANGE / 32;   // 56
    for (int ch = 0; ch < NCH; ch++) {
        if (ch + 1 < NCH) load_chunk((ch + 1) & 1, kbase + (ch + 1) * 32);
        CP_COMMIT();
        CP_WAIT1();
        __syncthreads();
        mma_chunk((__nv_bfloat16*)smem + (ch & 1) * STAGE_ELEMS,
                  wm, wn, arow, akoff, brow, bkoff, f);
        __syncthreads();
    }

    float* Gp = &d_Gs[s][((size_t)p * TT) * DD + d0];
    #pragma unroll
    for (int mi = 0; mi < 2; mi++)
        #pragma unroll
        for (int nj = 0; nj < 8; nj++) {
            int row = wm + mi * 16 + (lane >> 2);
            int col = wn + nj * 8 + (lane & 3) * 2;
            *(float2*)&Gp[(size_t)row * DD + col] = make_float2(f.C[mi][nj][0], f.C[mi][nj][1]);
            *(float2*)&Gp[(size_t)(row + 8) * DD + col] = make_float2(f.C[mi][nj][2], f.C[mi][nj][3]);
        }
}

// ---------------- kernel 5: per-pair score S[p] ----------------
__global__ void __launch_bounds__(256) k_score(const float* __restrict__ text) {
    const int p = blockIdx.x, i = p >> 3, j = p & 7;
    __shared__ float sbeta[TT * MM];
    __shared__ float sls[MM];
    __shared__ float sdiag[TT];
    __shared__ float snrm[MM], sdot[MM];
    __shared__ float Es[TT * 128];
    const int tid = threadIdx.x, lane = tid & 31, warp = tid >> 5;
    const float* E = text + (size_t)j * TT * DD;

    for (int idx = tid; idx < TT * MM; idx += 256)
        sbeta[idx] = d_sExp[(size_t)p * TT * MM + idx];
    if (tid < MM) { snrm[tid] = 0.f; sdot[tid] = 0.f; }
    __syncthreads();
    if (tid < MM) {
        float s = 0.f;
        for (int t = 0; t < TT; t++) s += sbeta[t * MM + tid];
        sls[tid] = 1.0f / s;
    }
    __syncthreads();
    for (int idx = tid; idx < TT * MM; idx += 256) {
        float v = sbeta[idx] * sls[idx % MM];
        sbeta[idx] = v;
        if (i == j) d_betas[(size_t)i * TT * MM + idx] = v;
    }
    __syncthreads();

    for (int t = warp; t < TT; t += 8) {
        const size_t off = ((size_t)p * TT + t) * DD;
        const float* Er = E + (size_t)t * DD;
        float s = 0.f;
        for (int d = lane; d < DD; d += 32) {
            float g = d_Gs[0][off + d] + d_Gs[1][off + d]
                    + d_Gs[2][off + d] + d_Gs[3][off + d];
            s = fmaf(g, Er[d], s);
        }
        #pragma unroll
        for (int o = 16; o; o >>= 1) s += __shfl_down_sync(0xffffffffu, s, o);
        if (lane == 0) sdiag[t] = s / d_Zt[p * TT + t];
    }

    const float* U = d_u + (size_t)i * MM * DD;
    const int grp = tid >> 7;
    const int dl = tid & 127;
    for (int d0 = 0; d0 < DD; d0 += 128) {
        __syncthreads();
        for (int idx = tid; idx < TT * 128; idx += 256) {
            int t = idx >> 7, dloc = idx & 127;
            Es[idx] = E[(size_t)t * DD + d0 + dloc];
        }
        __syncthreads();
        for (int m = grp; m < MM; m += 2) {
            float v = 0.f;
            #pragma unroll 16
            for (int t = 0; t < TT; t++)
                v = fmaf(sbeta[t * MM + m], Es[t * 128 + dl], v);
            float nr = v * v;
            float dt = v * U[(size_t)m * DD + d0 + dl];
            #pragma unroll
            for (int o = 16; o; o >>= 1) {
                nr += __shfl_down_sync(0xffffffffu, nr, o);
                dt += __shfl_down_sync(0xffffffffu, dt, o);
            }
            if (lane == 0) { atomicAdd(&snrm[m], nr); atomicAdd(&sdot[m], dt); }
        }
    }
    __syncthreads();
    if (tid == 0) {
        float se = 0.f;
        for (int t = 0; t < TT; t++) se += expf(G2 * sdiag[t]);
        float r_qd = (1.0f / G2) * logf(se);
        float sm = 0.f;
        for (int m = 0; m < MM; m++)
            sm += expf(sdot[m] / ((float)HWW * sqrtf(snrm[m])));
        d_S[p] = r_qd + (1.0f / G2) * logf(sm);
    }
}

// ---------------- kernel 6: final scalar ----------------
__global__ void __launch_bounds__(256) k_final(const int* __restrict__ spinds,
                                               float* __restrict__ out) {
    __shared__ float sbm[TT * MM];
    __shared__ float red[8];
    __shared__ float regsum;
    const int tid = threadIdx.x, lane = tid & 31, warp = tid >> 5;
    if (tid == 0) regsum = 0.f;
    for (int b = 0; b < BB; b++) {
        __syncthreads();
        for (int idx = tid; idx < TT * MM; idx += 256)
            sbm[idx] = d_betas[(size_t)b * TT * MM + idx];
        __syncthreads();
        float lsum = 0.f;
        for (int idx = tid; idx < MM * MM; idx += 256) {
            int a = idx / MM, c = idx % MM;
            float v = 0.f;
            for (int t = 0; t < TT; t++)
                v = fmaf(sbm[t * MM + a], sbm[t * MM + c], v);
            lsum = fmaf(v, v, lsum);
        }
        for (int t = tid; t < TT; t += 256) {
            float v = 0.f;
            for (int m = 0; m < MM; m++)
                v = fmaf(sbm[t * MM + m], sbm[t * MM + m], v);
            lsum -= v * v;
        }
        #pragma unroll
        for (int o = 16; o; o >>= 1)
            lsum += __shfl_down_sync(0xffffffffu, lsum, o);
        if (lane == 0) red[warp] = lsum;
        __syncthreads();
        if (tid == 0) {
            float s = 0.f;
            for (int w = 0; w < 8; w++) s += red[w];
            regsum += sqrtf(fmaxf(s, 0.f));
        }
    }
    __syncthreads();
    if (tid == 0) {
        float l1 = 0.f, l2 = 0.f;
        for (int a = 0; a < BB; a++) {
            float num = expf(d_S[a * BB + a]);
            float pdq = 0.f, pqd = 0.f;
            for (int k = 0; k < 5; k++) {
                int sp = spinds[a * 5 + k];
                pdq += expf(d_S[a * BB + sp]);
                pqd += expf(d_S[sp * BB + a]);
            }
            l1 += num / pdq;
            l2 += num / pqd;
        }
        out[0] = -(l1 / BB) - (l2 / BB) + regsum / (float)(BB * TT * MM);
    }
}

// ---------------- launcher ----------------
extern "C" void kernel_launch(void* const* d_in, const int* in_sizes, int n_in,
                              void* d_out, int out_size) {
    const float* image  = (const float*)d_in[0];
    const float* text   = (const float*)d_in[1];
    const int*   spinds = (const int*)d_in[3];
    float* out = (float*)d_out;

    cudaFuncSetAttribute(k_sim_mma, cudaFuncAttributeMaxDynamicSharedMemorySize, SMEM_DYN);
    cudaFuncSetAttribute(k_gmm_mma, cudaFuncAttributeMaxDynamicSharedMemorySize, SMEM_DYN);

    k_init<<<1024, 256>>>();
    k_prep<<<(BB * TT * DD) / 256, 256>>>(text);
    {
        dim3 g(16, MM, BB);
        k_transpose<<<g, 256>>>(image);
    }
    {
        dim3 g(MM, BB);
        k_u<<<g, 256>>>();
    }
    {
        dim3 g(NNP / 256, PP);          // 28 x 64
        k_sim_mma<<<g, 256, SMEM_DYN>>>();
    }
    {
        dim3 g(DD / 256, GSPLIT, PP);   // 2 x 4 x 64
        k_gmm_mma<<<g, 256, SMEM_DYN>>>();
    }
    k_score<<<PP, 256>>>(text);
    k_final<<<1, 256>>>(spinds, out);
}